// round 1
// baseline (speedup 1.0000x reference)
#include <cuda_runtime.h>

#define B_SZ   8192
#define EPER   64
#define PPER   16
#define D_SZ   128
#define MN     64
#define MD     128
#define OUTD   256
#define TM     32
#define NTHR   256

// dynamic smem layout (floats/ints):
//   s_eidx [TM*EPER]  int    8192 B
//   s_pidx [TM*PPER]  int    2048 B
//   s_mc   [TM*MN]    float  8192 B
//   s_sem  [TM*D]     float 16384 B
//   s_h1   [TM*MD]    float 16384 B
//   s_m2   [TM*MD]    float 16384 B
// total = 67584 B
#define SMEM_BYTES 67584

__global__ __launch_bounds__(NTHR, 2)
void subgraph_fused_kernel(const int*   __restrict__ eidx,
                           const int*   __restrict__ pidx,
                           const float* __restrict__ mc,
                           const float* __restrict__ etab,
                           const float* __restrict__ ptab,
                           const float* __restrict__ W1,
                           const float* __restrict__ b1,
                           const float* __restrict__ W2,
                           const float* __restrict__ b2,
                           const float* __restrict__ Wf,
                           const float* __restrict__ bf,
                           float*       __restrict__ out)
{
    extern __shared__ char smem_raw[];
    int*   s_eidx = (int*)smem_raw;                    // TM*EPER
    int*   s_pidx = s_eidx + TM * EPER;                // TM*PPER
    float* s_mc   = (float*)(s_pidx + TM * PPER);      // TM*MN
    float* s_sem  = s_mc  + TM * MN;                   // TM*D
    float* s_h1   = s_sem + TM * D_SZ;                 // TM*MD
    float* s_m2   = s_h1  + TM * MD;                   // TM*MD

    const int tid     = threadIdx.x;
    const int rowBase = blockIdx.x * TM;

    // ---- stage 0: cooperative loads of indices + motif counts (coalesced) ----
    #pragma unroll
    for (int i = tid; i < TM * EPER; i += NTHR) s_eidx[i] = eidx[rowBase * EPER + i];
    #pragma unroll
    for (int i = tid; i < TM * PPER; i += NTHR) s_pidx[i] = pidx[rowBase * PPER + i];
    #pragma unroll
    for (int i = tid; i < TM * MN; i += NTHR)   s_mc[i]   = mc[rowBase * MN + i];
    __syncthreads();

    const int lane = tid & (D_SZ - 1);   // 0..127 : feature dim
    const int grp  = tid >> 7;           // 0/1    : row-group

    // ---- stage 1: gather + mean pool (L2-bound; coalesced 512B per row) ----
    for (int rr = grp; rr < TM; rr += 2) {
        float es0 = 0.f, es1 = 0.f;
        #pragma unroll 8
        for (int e = 0; e < EPER; e += 2) {
            int i0 = s_eidx[rr * EPER + e];
            int i1 = s_eidx[rr * EPER + e + 1];
            es0 += etab[(size_t)i0 * D_SZ + lane];
            es1 += etab[(size_t)i1 * D_SZ + lane];
        }
        float ps0 = 0.f, ps1 = 0.f;
        #pragma unroll
        for (int e = 0; e < PPER; e += 2) {
            int i0 = s_pidx[rr * PPER + e];
            int i1 = s_pidx[rr * PPER + e + 1];
            ps0 += ptab[(size_t)i0 * D_SZ + lane];
            ps1 += ptab[(size_t)i1 * D_SZ + lane];
        }
        s_sem[rr * D_SZ + lane] =
            ((es0 + es1) * (1.f / EPER) + (ps0 + ps1) * (1.f / PPER)) * 0.5f;
    }
    __syncthreads();

    // ---- stage 2: h1 = relu(mc @ W1 + b1) ----
    // thread = (grp, col=lane); each thread reads each W1 element ONCE,
    // reuses it across 16 rows held in registers.
    {
        float acc[16];
        const float bb = b1[lane];
        #pragma unroll
        for (int r = 0; r < 16; r++) acc[r] = bb;
        for (int i = 0; i < MN; i++) {
            const float w = W1[i * MD + lane];
            #pragma unroll
            for (int r = 0; r < 16; r++)
                acc[r] += s_mc[(grp + 2 * r) * MN + i] * w;
        }
        #pragma unroll
        for (int r = 0; r < 16; r++)
            s_h1[(grp + 2 * r) * MD + lane] = fmaxf(acc[r], 0.f);
    }
    __syncthreads();

    // ---- stage 3: m2 = relu(h1 @ W2 + b2) ----
    {
        float acc[16];
        const float bb = b2[lane];
        #pragma unroll
        for (int r = 0; r < 16; r++) acc[r] = bb;
        for (int i = 0; i < MD; i++) {
            const float w = W2[i * MD + lane];
            #pragma unroll
            for (int r = 0; r < 16; r++)
                acc[r] += s_h1[(grp + 2 * r) * MD + i] * w;
        }
        #pragma unroll
        for (int r = 0; r < 16; r++)
            s_m2[(grp + 2 * r) * MD + lane] = fmaxf(acc[r], 0.f);
    }
    __syncthreads();

    // ---- stage 4: out = relu(concat(sem, m2) @ Wf + bf) ----
    // thread micro-tile: 8 rows x 4 cols. tx = col-group (float4), ty = row-group.
    {
        const int tx = tid & 63;   // cols 4*tx .. 4*tx+3
        const int ty = tid >> 6;   // rows 8*ty .. 8*ty+7

        float acc[8][4];
        #pragma unroll
        for (int r = 0; r < 8; r++)
            #pragma unroll
            for (int c = 0; c < 4; c++) acc[r][c] = 0.f;

        // k = 0..127 : semantic half
        for (int k = 0; k < D_SZ; k++) {
            const float4 w = ((const float4*)(Wf + (size_t)k * OUTD))[tx];
            #pragma unroll
            for (int r = 0; r < 8; r++) {
                const float a = s_sem[(8 * ty + r) * D_SZ + k];
                acc[r][0] += a * w.x;
                acc[r][1] += a * w.y;
                acc[r][2] += a * w.z;
                acc[r][3] += a * w.w;
            }
        }
        // k = 128..255 : motif half
        for (int k = 0; k < MD; k++) {
            const float4 w = ((const float4*)(Wf + (size_t)(D_SZ + k) * OUTD))[tx];
            #pragma unroll
            for (int r = 0; r < 8; r++) {
                const float a = s_m2[(8 * ty + r) * MD + k];
                acc[r][0] += a * w.x;
                acc[r][1] += a * w.y;
                acc[r][2] += a * w.z;
                acc[r][3] += a * w.w;
            }
        }

        const float4 bfv = ((const float4*)bf)[tx];
        #pragma unroll
        for (int r = 0; r < 8; r++) {
            float4 o;
            o.x = fmaxf(acc[r][0] + bfv.x, 0.f);
            o.y = fmaxf(acc[r][1] + bfv.y, 0.f);
            o.z = fmaxf(acc[r][2] + bfv.z, 0.f);
            o.w = fmaxf(acc[r][3] + bfv.w, 0.f);
            ((float4*)(out + (size_t)(rowBase + 8 * ty + r) * OUTD))[tx] = o;
        }
    }
}

extern "C" void kernel_launch(void* const* d_in, const int* in_sizes, int n_in,
                              void* d_out, int out_size)
{
    const int*   eidx = (const int*)d_in[0];
    const int*   pidx = (const int*)d_in[1];
    const float* mc   = (const float*)d_in[2];
    const float* etab = (const float*)d_in[3];
    const float* ptab = (const float*)d_in[4];
    const float* W1   = (const float*)d_in[5];
    const float* b1   = (const float*)d_in[6];
    const float* W2   = (const float*)d_in[7];
    const float* b2   = (const float*)d_in[8];
    const float* Wf   = (const float*)d_in[9];
    const float* bf   = (const float*)d_in[10];
    float* out = (float*)d_out;

    cudaFuncSetAttribute(subgraph_fused_kernel,
                         cudaFuncAttributeMaxDynamicSharedMemorySize, SMEM_BYTES);

    subgraph_fused_kernel<<<B_SZ / TM, NTHR, SMEM_BYTES>>>(
        eidx, pidx, mc, etab, ptab, W1, b1, W2, b2, Wf, bf, out);
}

// round 2
// speedup vs baseline: 1.2854x; 1.2854x over previous
#include <cuda_runtime.h>

#define B_SZ   8192
#define EPER   64
#define PPER   16
#define D_SZ   128
#define MN     64
#define MD     128
#define OUTD   256
#define TM     32
#define NTHR   256

// dynamic smem layout (bytes):
//   s_eidx [TM*EPER] int    8192   \
//   s_pidx [TM*PPER] int    2048    > 18432 B  (dead after stage 2; s_m2 aliases here)
//   s_mc   [TM*MN]   float  8192   /
//   s_sem  [TM*D]    float 16384
//   s_h1   [TM*MD]   float 16384
// total = 51200 B
#define SMEM_BYTES 51200

__global__ __launch_bounds__(NTHR, 2)
void subgraph_fused_kernel(const int*   __restrict__ eidx,
                           const int*   __restrict__ pidx,
                           const float* __restrict__ mc,
                           const float* __restrict__ etab,
                           const float* __restrict__ ptab,
                           const float* __restrict__ W1,
                           const float* __restrict__ b1,
                           const float* __restrict__ W2,
                           const float* __restrict__ b2,
                           const float* __restrict__ Wf,
                           const float* __restrict__ bf,
                           float*       __restrict__ out)
{
    extern __shared__ char smem_raw[];
    int*   s_eidx = (int*)smem_raw;                    // TM*EPER
    int*   s_pidx = s_eidx + TM * EPER;                // TM*PPER
    float* s_mc   = (float*)(s_pidx + TM * PPER);      // TM*MN
    float* s_sem  = s_mc  + TM * MN;                   // TM*D
    float* s_h1   = s_sem + TM * D_SZ;                 // TM*MD
    float* s_m2   = (float*)smem_raw;                  // aliases eidx/pidx/mc (16384 <= 18432)

    const int tid     = threadIdx.x;
    const int rowBase = blockIdx.x * TM;

    // ---- stage 0: cooperative vectorized staging of indices + motif counts ----
    {
        const int4* geidx = (const int4*)(eidx + rowBase * EPER);   // 512 int4
        int4*       sidx4 = (int4*)s_eidx;
        #pragma unroll
        for (int i = tid; i < TM * EPER / 4; i += NTHR) sidx4[i] = geidx[i];

        const int4* gpidx = (const int4*)(pidx + rowBase * PPER);   // 128 int4
        int4*       spid4 = (int4*)s_pidx;
        if (tid < TM * PPER / 4) spid4[tid] = gpidx[tid];

        const float4* gmc = (const float4*)(mc + rowBase * MN);     // 512 float4
        float4*       smc4 = (float4*)s_mc;
        #pragma unroll
        for (int i = tid; i < TM * MN / 4; i += NTHR) smc4[i] = gmc[i];
    }
    __syncthreads();

    const int warp  = tid >> 5;
    const int wlane = tid & 31;

    // ---- stage 1: gather + mean pool, float4-vectorized ----
    // warp w handles rows [4w, 4w+4); each lane owns features [4*wlane, 4*wlane+4)
    {
        const float4* etab4 = (const float4*)etab;
        const float4* ptab4 = (const float4*)ptab;
        const int r0 = warp * 4;

        float4 acc[4];
        #pragma unroll
        for (int r = 0; r < 4; r++) acc[r] = make_float4(0.f, 0.f, 0.f, 0.f);

        // entity gather: 4 rows x float4 per iteration -> 8 loads in flight w/ unroll 2
        #pragma unroll 4
        for (int e = 0; e < EPER; e++) {
            #pragma unroll
            for (int r = 0; r < 4; r++) {
                const int ix = s_eidx[(r0 + r) * EPER + e];
                const float4 v = etab4[(size_t)ix * 32 + wlane];
                acc[r].x += v.x; acc[r].y += v.y; acc[r].z += v.z; acc[r].w += v.w;
            }
        }
        float4 accP[4];
        #pragma unroll
        for (int r = 0; r < 4; r++) accP[r] = make_float4(0.f, 0.f, 0.f, 0.f);
        #pragma unroll 4
        for (int e = 0; e < PPER; e++) {
            #pragma unroll
            for (int r = 0; r < 4; r++) {
                const int ix = s_pidx[(r0 + r) * PPER + e];
                const float4 v = ptab4[(size_t)ix * 32 + wlane];
                accP[r].x += v.x; accP[r].y += v.y; accP[r].z += v.z; accP[r].w += v.w;
            }
        }

        const float se = 0.5f / EPER, sp = 0.5f / PPER;
        #pragma unroll
        for (int r = 0; r < 4; r++) {
            float4 s;
            s.x = acc[r].x * se + accP[r].x * sp;
            s.y = acc[r].y * se + accP[r].y * sp;
            s.z = acc[r].z * se + accP[r].z * sp;
            s.w = acc[r].w * se + accP[r].w * sp;
            ((float4*)(s_sem + (r0 + r) * D_SZ))[wlane] = s;
        }
    }
    __syncthreads();

    const int lane = tid & (D_SZ - 1);   // 0..127 : feature column
    const int grp  = tid >> 7;           // 0/1    : row-group

    // ---- stage 2: h1 = relu(mc @ W1 + b1) ----
    {
        float a[16];
        const float bb = b1[lane];
        #pragma unroll
        for (int r = 0; r < 16; r++) a[r] = bb;
        for (int i = 0; i < MN; i++) {
            const float w = W1[i * MD + lane];
            #pragma unroll
            for (int r = 0; r < 16; r++)
                a[r] += s_mc[(grp + 2 * r) * MN + i] * w;
        }
        #pragma unroll
        for (int r = 0; r < 16; r++)
            s_h1[(grp + 2 * r) * MD + lane] = fmaxf(a[r], 0.f);
    }
    __syncthreads();

    // ---- stage 3: m2 = relu(h1 @ W2 + b2) (writes alias over dead idx/mc smem) ----
    {
        float a[16];
        const float bb = b2[lane];
        #pragma unroll
        for (int r = 0; r < 16; r++) a[r] = bb;
        for (int i = 0; i < MD; i++) {
            const float w = W2[i * MD + lane];
            #pragma unroll
            for (int r = 0; r < 16; r++)
                a[r] += s_h1[(grp + 2 * r) * MD + i] * w;
        }
        __syncthreads();   // ensure all stage-2/1 readers of aliased region are done
        #pragma unroll
        for (int r = 0; r < 16; r++)
            s_m2[(grp + 2 * r) * MD + lane] = fmaxf(a[r], 0.f);
    }
    __syncthreads();

    // ---- stage 4: out = relu(concat(sem, m2) @ Wf + bf), 8x4 micro-tile ----
    {
        const int tx = tid & 63;   // cols 4*tx .. 4*tx+3
        const int ty = tid >> 6;   // rows 8*ty .. 8*ty+7

        float acc[8][4];
        #pragma unroll
        for (int r = 0; r < 8; r++)
            #pragma unroll
            for (int c = 0; c < 4; c++) acc[r][c] = 0.f;

        for (int k = 0; k < D_SZ; k++) {
            const float4 w = ((const float4*)(Wf + (size_t)k * OUTD))[tx];
            #pragma unroll
            for (int r = 0; r < 8; r++) {
                const float a = s_sem[(8 * ty + r) * D_SZ + k];
                acc[r][0] += a * w.x;
                acc[r][1] += a * w.y;
                acc[r][2] += a * w.z;
                acc[r][3] += a * w.w;
            }
        }
        for (int k = 0; k < MD; k++) {
            const float4 w = ((const float4*)(Wf + (size_t)(D_SZ + k) * OUTD))[tx];
            #pragma unroll
            for (int r = 0; r < 8; r++) {
                const float a = s_m2[(8 * ty + r) * MD + k];
                acc[r][0] += a * w.x;
                acc[r][1] += a * w.y;
                acc[r][2] += a * w.z;
                acc[r][3] += a * w.w;
            }
        }

        const float4 bfv = ((const float4*)bf)[tx];
        #pragma unroll
        for (int r = 0; r < 8; r++) {
            float4 o;
            o.x = fmaxf(acc[r][0] + bfv.x, 0.f);
            o.y = fmaxf(acc[r][1] + bfv.y, 0.f);
            o.z = fmaxf(acc[r][2] + bfv.z, 0.f);
            o.w = fmaxf(acc[r][3] + bfv.w, 0.f);
            ((float4*)(out + (size_t)(rowBase + 8 * ty + r) * OUTD))[tx] = o;
        }
    }
}

extern "C" void kernel_launch(void* const* d_in, const int* in_sizes, int n_in,
                              void* d_out, int out_size)
{
    const int*   eidx = (const int*)d_in[0];
    const int*   pidx = (const int*)d_in[1];
    const float* mc   = (const float*)d_in[2];
    const float* etab = (const float*)d_in[3];
    const float* ptab = (const float*)d_in[4];
    const float* W1   = (const float*)d_in[5];
    const float* b1   = (const float*)d_in[6];
    const float* W2   = (const float*)d_in[7];
    const float* b2   = (const float*)d_in[8];
    const float* Wf   = (const float*)d_in[9];
    const float* bf   = (const float*)d_in[10];
    float* out = (float*)d_out;

    cudaFuncSetAttribute(subgraph_fused_kernel,
                         cudaFuncAttributeMaxDynamicSharedMemorySize, SMEM_BYTES);

    subgraph_fused_kernel<<<B_SZ / TM, NTHR, SMEM_BYTES>>>(
        eidx, pidx, mc, etab, ptab, W1, b1, W2, b2, Wf, bf, out);
}

// round 3
// speedup vs baseline: 1.4013x; 1.0902x over previous
#include <cuda_runtime.h>

#define B_SZ   8192
#define EPER   64
#define PPER   16
#define D_SZ   128
#define MN     64
#define MD     128
#define OUTD   256
#define TM     16
#define NTHR   256

// dynamic smem layout (bytes):
//   s_eidx [TM*EPER] int    4096   \
//   s_pidx [TM*PPER] int    1024    > 9216 B  (dead after stage 2; s_m2 aliases: 8192 <= 9216)
//   s_mc   [TM*MN]   float  4096   /
//   s_sem  [TM*D]    float  8192
//   s_h1   [TM*MD]   float  8192
// total = 25600 B
#define SMEM_BYTES 25600

__global__ __launch_bounds__(NTHR, 3)
void subgraph_fused_kernel(const int*   __restrict__ eidx,
                           const int*   __restrict__ pidx,
                           const float* __restrict__ mc,
                           const float* __restrict__ etab,
                           const float* __restrict__ ptab,
                           const float* __restrict__ W1,
                           const float* __restrict__ b1,
                           const float* __restrict__ W2,
                           const float* __restrict__ b2,
                           const float* __restrict__ Wf,
                           const float* __restrict__ bf,
                           float*       __restrict__ out)
{
    extern __shared__ char smem_raw[];
    int*   s_eidx = (int*)smem_raw;                    // TM*EPER
    int*   s_pidx = s_eidx + TM * EPER;                // TM*PPER
    float* s_mc   = (float*)(s_pidx + TM * PPER);      // TM*MN
    float* s_sem  = s_mc  + TM * MN;                   // TM*D
    float* s_h1   = s_sem + TM * D_SZ;                 // TM*MD
    float* s_m2   = (float*)smem_raw;                  // aliases idx/mc region

    const int tid     = threadIdx.x;
    const int rowBase = blockIdx.x * TM;

    // ---- stage 0: cooperative vectorized staging ----
    {
        const int4* geidx = (const int4*)(eidx + rowBase * EPER);   // 256 int4
        int4*       sidx4 = (int4*)s_eidx;
        if (tid < TM * EPER / 4) sidx4[tid] = geidx[tid];

        const int4* gpidx = (const int4*)(pidx + rowBase * PPER);   // 64 int4
        int4*       spid4 = (int4*)s_pidx;
        if (tid < TM * PPER / 4) spid4[tid] = gpidx[tid];

        const float4* gmc  = (const float4*)(mc + rowBase * MN);    // 256 float4
        float4*       smc4 = (float4*)s_mc;
        if (tid < TM * MN / 4) smc4[tid] = gmc[tid];
    }
    __syncthreads();

    const int warp  = tid >> 5;
    const int wlane = tid & 31;

    // ---- stage 1: gather + mean pool, float4-vectorized ----
    // warp w handles rows [2w, 2w+2); lane owns features [4*wlane, 4*wlane+4)
    {
        const float4* etab4 = (const float4*)etab;
        const float4* ptab4 = (const float4*)ptab;
        const int r0 = warp * 2;

        float4 acc[2];
        acc[0] = make_float4(0.f, 0.f, 0.f, 0.f);
        acc[1] = make_float4(0.f, 0.f, 0.f, 0.f);

        #pragma unroll 8
        for (int e = 0; e < EPER; e++) {
            #pragma unroll
            for (int r = 0; r < 2; r++) {
                const int ix = s_eidx[(r0 + r) * EPER + e];
                const float4 v = etab4[(size_t)ix * 32 + wlane];
                acc[r].x += v.x; acc[r].y += v.y; acc[r].z += v.z; acc[r].w += v.w;
            }
        }
        float4 accP[2];
        accP[0] = make_float4(0.f, 0.f, 0.f, 0.f);
        accP[1] = make_float4(0.f, 0.f, 0.f, 0.f);
        #pragma unroll 8
        for (int e = 0; e < PPER; e++) {
            #pragma unroll
            for (int r = 0; r < 2; r++) {
                const int ix = s_pidx[(r0 + r) * PPER + e];
                const float4 v = ptab4[(size_t)ix * 32 + wlane];
                accP[r].x += v.x; accP[r].y += v.y; accP[r].z += v.z; accP[r].w += v.w;
            }
        }

        const float se = 0.5f / EPER, sp = 0.5f / PPER;
        #pragma unroll
        for (int r = 0; r < 2; r++) {
            float4 s;
            s.x = acc[r].x * se + accP[r].x * sp;
            s.y = acc[r].y * se + accP[r].y * sp;
            s.z = acc[r].z * se + accP[r].z * sp;
            s.w = acc[r].w * se + accP[r].w * sp;
            ((float4*)(s_sem + (r0 + r) * D_SZ))[wlane] = s;
        }
    }
    __syncthreads();

    const int lane = tid & (D_SZ - 1);   // 0..127 : feature column
    const int grp  = tid >> 7;           // 0/1    : row-group

    // ---- stage 2: h1 = relu(mc @ W1 + b1) ----
    {
        float a[8];
        const float bb = b1[lane];
        #pragma unroll
        for (int r = 0; r < 8; r++) a[r] = bb;
        for (int i = 0; i < MN; i++) {
            const float w = W1[i * MD + lane];
            #pragma unroll
            for (int r = 0; r < 8; r++)
                a[r] += s_mc[(grp + 2 * r) * MN + i] * w;
        }
        #pragma unroll
        for (int r = 0; r < 8; r++)
            s_h1[(grp + 2 * r) * MD + lane] = fmaxf(a[r], 0.f);
    }
    __syncthreads();

    // ---- stage 3: m2 = relu(h1 @ W2 + b2) (writes alias over dead idx/mc smem) ----
    {
        float a[8];
        const float bb = b2[lane];
        #pragma unroll
        for (int r = 0; r < 8; r++) a[r] = bb;
        for (int i = 0; i < MD; i++) {
            const float w = W2[i * MD + lane];
            #pragma unroll
            for (int r = 0; r < 8; r++)
                a[r] += s_h1[(grp + 2 * r) * MD + i] * w;
        }
        __syncthreads();   // all readers of aliased region done
        #pragma unroll
        for (int r = 0; r < 8; r++)
            s_m2[(grp + 2 * r) * MD + lane] = fmaxf(a[r], 0.f);
    }
    __syncthreads();

    // ---- stage 4: out = relu(concat(sem, m2) @ Wf + bf), 4x4 micro-tile ----
    {
        const int tx = tid & 63;   // cols 4*tx .. 4*tx+3
        const int ty = tid >> 6;   // rows 4*ty .. 4*ty+3

        float acc[4][4];
        #pragma unroll
        for (int r = 0; r < 4; r++)
            #pragma unroll
            for (int c = 0; c < 4; c++) acc[r][c] = 0.f;

        for (int k = 0; k < D_SZ; k++) {
            const float4 w = ((const float4*)(Wf + (size_t)k * OUTD))[tx];
            #pragma unroll
            for (int r = 0; r < 4; r++) {
                const float a = s_sem[(4 * ty + r) * D_SZ + k];
                acc[r][0] += a * w.x;
                acc[r][1] += a * w.y;
                acc[r][2] += a * w.z;
                acc[r][3] += a * w.w;
            }
        }
        for (int k = 0; k < MD; k++) {
            const float4 w = ((const float4*)(Wf + (size_t)(D_SZ + k) * OUTD))[tx];
            #pragma unroll
            for (int r = 0; r < 4; r++) {
                const float a = s_m2[(4 * ty + r) * MD + k];
                acc[r][0] += a * w.x;
                acc[r][1] += a * w.y;
                acc[r][2] += a * w.z;
                acc[r][3] += a * w.w;
            }
        }

        const float4 bfv = ((const float4*)bf)[tx];
        #pragma unroll
        for (int r = 0; r < 4; r++) {
            float4 o;
            o.x = fmaxf(acc[r][0] + bfv.x, 0.f);
            o.y = fmaxf(acc[r][1] + bfv.y, 0.f);
            o.z = fmaxf(acc[r][2] + bfv.z, 0.f);
            o.w = fmaxf(acc[r][3] + bfv.w, 0.f);
            ((float4*)(out + (size_t)(rowBase + 4 * ty + r) * OUTD))[tx] = o;
        }
    }
}

extern "C" void kernel_launch(void* const* d_in, const int* in_sizes, int n_in,
                              void* d_out, int out_size)
{
    const int*   eidx = (const int*)d_in[0];
    const int*   pidx = (const int*)d_in[1];
    const float* mc   = (const float*)d_in[2];
    const float* etab = (const float*)d_in[3];
    const float* ptab = (const float*)d_in[4];
    const float* W1   = (const float*)d_in[5];
    const float* b1   = (const float*)d_in[6];
    const float* W2   = (const float*)d_in[7];
    const float* b2   = (const float*)d_in[8];
    const float* Wf   = (const float*)d_in[9];
    const float* bf   = (const float*)d_in[10];
    float* out = (float*)d_out;

    cudaFuncSetAttribute(subgraph_fused_kernel,
                         cudaFuncAttributeMaxDynamicSharedMemorySize, SMEM_BYTES);

    subgraph_fused_kernel<<<B_SZ / TM, NTHR, SMEM_BYTES>>>(
        eidx, pidx, mc, etab, ptab, W1, b1, W2, b2, Wf, bf, out);
}